// round 1
// baseline (speedup 1.0000x reference)
#include <cuda_runtime.h>
#include <cuda_bf16.h>
#include <math.h>

// ---------------------------------------------------------------------------
// MemoryTransformerXL forward, fp32.
// B=2, DEPTH=4, HEADS=8, DIM=1024, DH=128, SEQ=1024, MEM=1024, LMEM=256,
// VOCAB=32000, KVL=2304, FF=4096.
// ---------------------------------------------------------------------------

#define NB (2)
#define NSEQ (1024)
#define NDIM (1024)
#define NHEADS (8)
#define NDH (128)
#define NMEM (1024)
#define NLMEM (256)
#define NKVL (2304)
#define NDEPTH (4)
#define NVOCAB (32000)
#define NFF (4096)

// scratch layout (floats)
#define SZ_H    (2097152LL)            // (B*SEQ, DIM)
#define SZ_HID  (8388608LL)            // (DEPTH,B,SEQ,DIM)
#define SZ_LN   (2097152LL)
#define SZ_Q    (2097152LL)
#define SZ_KV   (9437184LL)            // (B, 2304, 2048)
#define SZ_QK   (37748736LL)           // (16, 1024, 2304)
#define SZ_QPE  (37748736LL)
#define SZ_AOUT (2097152LL)
#define SZ_FF   (8388608LL)            // (2048, 4096)
#define SZ_NL   (2097152LL)
#define SZ_MQ   (2097152LL)
#define SZ_MKV  (37748736LL)           // (8, 2304, 2048)
#define SZ_CTX  (1048576LL)            // (64, 128, 128)
#define SZ_MOUT (2097152LL)
#define SZ_TOTAL (155189248LL)

__device__ float g_scratch[SZ_TOTAL];

// ---------------------------------------------------------------------------
// General batched fp32 GEMM: C = act(alpha*A@B + bias) + resid
// Tiles: 128x128x16, 256 threads, 8x8 per thread. All M%128==N%128==K%16==0.
// Batch offset: b1 = bz/bdiv, b2 = bz%bdiv; off = b1*s1 + b2*s2 (per matrix).
// transA: A stored (K,M) row-major with ld=lda.  transB: B stored (N,K).
// ---------------------------------------------------------------------------
__global__ void __launch_bounds__(256, 2) gemm_kernel(
    const float* __restrict__ A, const float* __restrict__ B,
    float* __restrict__ C, const float* __restrict__ Rsrc,
    const float* __restrict__ bias, const float* __restrict__ alphap,
    int M, int N, int K, int lda, int ldb, int ldc,
    long long sA1, long long sA2, long long sB1, long long sB2,
    long long sC1, long long sC2, int bdiv,
    int transA, int transB, float alpha, int act)
{
    __shared__ float As[16][128];
    __shared__ float Bs[16][128];
    int bz = blockIdx.z;
    int b1 = bz / bdiv, b2 = bz - b1 * bdiv;
    long long offA = (long long)b1 * sA1 + (long long)b2 * sA2;
    long long offB = (long long)b1 * sB1 + (long long)b2 * sB2;
    long long offC = (long long)b1 * sC1 + (long long)b2 * sC2;
    A += offA; B += offB; C += offC;
    if (Rsrc) Rsrc += offC;

    int m0 = blockIdx.y * 128, n0 = blockIdx.x * 128;
    int tid = threadIdx.x;
    int tx = tid & 15, ty = tid >> 4;

    float acc[8][8];
#pragma unroll
    for (int i = 0; i < 8; i++)
#pragma unroll
        for (int j = 0; j < 8; j++) acc[i][j] = 0.f;

    for (int k0 = 0; k0 < K; k0 += 16) {
        if (!transA) {
#pragma unroll
            for (int it = 0; it < 2; it++) {
                int v = tid * 2 + it;
                int m = v >> 2;
                int kq = (v & 3) << 2;
                float4 t = *(const float4*)(A + (long long)(m0 + m) * lda + (k0 + kq));
                As[kq + 0][m] = t.x; As[kq + 1][m] = t.y;
                As[kq + 2][m] = t.z; As[kq + 3][m] = t.w;
            }
        } else {
#pragma unroll
            for (int it = 0; it < 2; it++) {
                int v = tid * 2 + it;
                int k = v >> 5;
                int mq = (v & 31) << 2;
                float4 t = *(const float4*)(A + (long long)(k0 + k) * lda + (m0 + mq));
                *(float4*)&As[k][mq] = t;
            }
        }
        if (!transB) {
#pragma unroll
            for (int it = 0; it < 2; it++) {
                int v = tid * 2 + it;
                int k = v >> 5;
                int nq = (v & 31) << 2;
                float4 t = *(const float4*)(B + (long long)(k0 + k) * ldb + (n0 + nq));
                *(float4*)&Bs[k][nq] = t;
            }
        } else {
#pragma unroll
            for (int it = 0; it < 2; it++) {
                int v = tid * 2 + it;
                int n = v >> 2;
                int kq = (v & 3) << 2;
                float4 t = *(const float4*)(B + (long long)(n0 + n) * ldb + (k0 + kq));
                Bs[kq + 0][n] = t.x; Bs[kq + 1][n] = t.y;
                Bs[kq + 2][n] = t.z; Bs[kq + 3][n] = t.w;
            }
        }
        __syncthreads();
#pragma unroll
        for (int k = 0; k < 16; k++) {
            float af[8], bf[8];
            *(float4*)&af[0] = *(const float4*)&As[k][ty * 8];
            *(float4*)&af[4] = *(const float4*)&As[k][ty * 8 + 4];
            *(float4*)&bf[0] = *(const float4*)&Bs[k][tx * 8];
            *(float4*)&bf[4] = *(const float4*)&Bs[k][tx * 8 + 4];
#pragma unroll
            for (int i = 0; i < 8; i++)
#pragma unroll
                for (int j = 0; j < 8; j++)
                    acc[i][j] = fmaf(af[i], bf[j], acc[i][j]);
        }
        __syncthreads();
    }

    float a = alphap ? *alphap : alpha;
#pragma unroll
    for (int i = 0; i < 8; i++) {
        int m = m0 + ty * 8 + i;
#pragma unroll
        for (int j0 = 0; j0 < 8; j0 += 4) {
            int n = n0 + tx * 8 + j0;
            float4 o;
            float* po = &o.x;
#pragma unroll
            for (int j = 0; j < 4; j++) {
                float t = acc[i][j0 + j] * a;
                if (bias) t += bias[n + j];
                if (act == 1) t = 0.5f * t * (1.f + erff(t * 0.70710678118654752f));
                if (Rsrc) t += Rsrc[(long long)m * ldc + n + j];
                po[j] = t;
            }
            *(float4*)(C + (long long)m * ldc + n) = o;
        }
    }
}

// ---------------------------------------------------------------------------
// Embedding gather: h[row] = token_emb[x[row]]
// ---------------------------------------------------------------------------
__global__ void embed_kernel(const int* __restrict__ x, const float* __restrict__ emb,
                             float* __restrict__ h)
{
    int row = blockIdx.x;
    int tok = x[row];
    *(float4*)(h + (long long)row * NDIM + threadIdx.x * 4) =
        *(const float4*)(emb + (long long)tok * NDIM + threadIdx.x * 4);
}

// ---------------------------------------------------------------------------
// LayerNorm over last dim (1024). g/b may be null (plain LN).
// One block (256 thr) per row, 4 floats/thread.
// ---------------------------------------------------------------------------
__global__ void layernorm_kernel(const float* __restrict__ x, const float* __restrict__ g,
                                 const float* __restrict__ b, float* __restrict__ y)
{
    int tid = threadIdx.x;
    long long base = (long long)blockIdx.x * NDIM;
    float4 v = *(const float4*)(x + base + tid * 4);
    float s = v.x + v.y + v.z + v.w;
    float q = v.x * v.x + v.y * v.y + v.z * v.z + v.w * v.w;
#pragma unroll
    for (int o = 16; o > 0; o >>= 1) {
        s += __shfl_xor_sync(0xffffffffu, s, o);
        q += __shfl_xor_sync(0xffffffffu, q, o);
    }
    __shared__ float rs[8], rq[8];
    if ((tid & 31) == 0) { rs[tid >> 5] = s; rq[tid >> 5] = q; }
    __syncthreads();
    s = 0.f; q = 0.f;
#pragma unroll
    for (int j = 0; j < 8; j++) { s += rs[j]; q += rq[j]; }
    float mu = s * (1.f / 1024.f);
    float var = q * (1.f / 1024.f) - mu * mu;
    float rstd = rsqrtf(var + 1e-5f);
    float4 o;
    if (g) {
        float4 gv = *(const float4*)(g + tid * 4);
        float4 bv = *(const float4*)(b + tid * 4);
        o.x = (v.x - mu) * rstd * gv.x + bv.x;
        o.y = (v.y - mu) * rstd * gv.y + bv.y;
        o.z = (v.z - mu) * rstd * gv.z + bv.z;
        o.w = (v.w - mu) * rstd * gv.w + bv.w;
    } else {
        o.x = (v.x - mu) * rstd; o.y = (v.y - mu) * rstd;
        o.z = (v.z - mu) * rstd; o.w = (v.w - mu) * rstd;
    }
    *(float4*)(y + base + tid * 4) = o;
}

// ---------------------------------------------------------------------------
// Attention softmax with fused rel_shift + causal mask.
// logit[r,c] = scale*(qk[r,c] + qpe[r, c+1023-r]) for c <= r+1280, else masked.
// Writes softmax back into qk. grid = (1024 rows, 16 bh), 256 threads.
// ---------------------------------------------------------------------------
__global__ void attn_softmax_kernel(float* __restrict__ qk, const float* __restrict__ qpe)
{
    const float scale = 0.08838834764831845f;  // 128^-0.5
    int r = blockIdx.x;
    long long base = ((long long)blockIdx.y * NSEQ + r) * NKVL;
    float* row = qk + base;
    const float* prow = qpe + base;
    int tid = threadIdx.x;
    int nvalid = r + 1281;  // r <= 1023 -> nvalid <= 2304

    float vals[9];
    float lmax = -3.4e38f;
#pragma unroll
    for (int it = 0; it < 9; it++) {
        int c = tid + it * 256;
        float v = -3.4e38f;
        if (c < nvalid) v = scale * (row[c] + prow[c + 1023 - r]);
        vals[it] = v;
        lmax = fmaxf(lmax, v);
    }
    __shared__ float red[8];
#pragma unroll
    for (int o = 16; o > 0; o >>= 1) lmax = fmaxf(lmax, __shfl_xor_sync(0xffffffffu, lmax, o));
    if ((tid & 31) == 0) red[tid >> 5] = lmax;
    __syncthreads();
    float m = red[0];
#pragma unroll
    for (int j = 1; j < 8; j++) m = fmaxf(m, red[j]);
    __syncthreads();

    float lsum = 0.f;
#pragma unroll
    for (int it = 0; it < 9; it++) {
        float e = expf(vals[it] - m);  // masked -> exp(-huge) == 0
        vals[it] = e;
        lsum += e;
    }
#pragma unroll
    for (int o = 16; o > 0; o >>= 1) lsum += __shfl_xor_sync(0xffffffffu, lsum, o);
    if ((tid & 31) == 0) red[tid >> 5] = lsum;
    __syncthreads();
    float ssum = 0.f;
#pragma unroll
    for (int j = 0; j < 8; j++) ssum += red[j];
    float inv = 1.f / ssum;
#pragma unroll
    for (int it = 0; it < 9; it++) row[tid + it * 256] = vals[it] * inv;
}

// ---------------------------------------------------------------------------
// Memory-net q softmax: per 128-wide head chunk (axis=-1), scale then softmax.
// One block (8 warps) per row of 1024; warp w handles head w; 4 elems/lane.
// ---------------------------------------------------------------------------
__global__ void head_softmax_kernel(float* __restrict__ q)
{
    const float scale = 0.29730177875068026f;  // 128^-0.25
    int w = threadIdx.x >> 5, lane = threadIdx.x & 31;
    float* p = q + (long long)blockIdx.x * NDIM + w * NDH + lane * 4;
    float4 v = *(float4*)p;
    v.x *= scale; v.y *= scale; v.z *= scale; v.w *= scale;
    float m = fmaxf(fmaxf(v.x, v.y), fmaxf(v.z, v.w));
#pragma unroll
    for (int o = 16; o > 0; o >>= 1) m = fmaxf(m, __shfl_xor_sync(0xffffffffu, m, o));
    float4 e;
    e.x = expf(v.x - m); e.y = expf(v.y - m); e.z = expf(v.z - m); e.w = expf(v.w - m);
    float s = e.x + e.y + e.z + e.w;
#pragma unroll
    for (int o = 16; o > 0; o >>= 1) s += __shfl_xor_sync(0xffffffffu, s, o);
    float inv = 1.f / s;
    e.x *= inv; e.y *= inv; e.z *= inv; e.w *= inv;
    *(float4*)p = e;
}

// ---------------------------------------------------------------------------
// Memory-net k softmax over n (axis=-2): per (m*b, column) over 2304 rows.
// grid (8 col tiles, 8 mb), 128 threads (one column each). In place, k part
// of (2304, 2048) tile, ld = 2048. Online max/sum then normalize pass.
// ---------------------------------------------------------------------------
__global__ void col_softmax_kernel(float* __restrict__ kbuf)
{
    const float scale = 0.29730177875068026f;
    int mb = blockIdx.y;
    int col = blockIdx.x * 128 + threadIdx.x;
    float* p = kbuf + (long long)mb * NKVL * 2048 + col;
    float m = -3.4e38f, s = 0.f;
    for (int n = 0; n < NKVL; n++) {
        float v = p[(long long)n * 2048] * scale;
        if (v > m) { s = s * expf(m - v) + 1.f; m = v; }
        else s += expf(v - m);
    }
    float inv = 1.f / s;
    for (int n = 0; n < NKVL; n++) {
        float v = p[(long long)n * 2048] * scale;
        p[(long long)n * 2048] = expf(v - m) * inv;
    }
}

// ---------------------------------------------------------------------------
// Host-side launcher
// ---------------------------------------------------------------------------
static void gemm(const float* A, const float* B, float* C,
                 int M, int N, int K, int lda, int ldb, int ldc,
                 int batch = 1, int bdiv = 1,
                 long long sA1 = 0, long long sA2 = 0,
                 long long sB1 = 0, long long sB2 = 0,
                 long long sC1 = 0, long long sC2 = 0,
                 int tA = 0, int tB = 0,
                 const float* bias = nullptr, const float* resid = nullptr,
                 const float* alphap = nullptr, float alpha = 1.f, int act = 0)
{
    dim3 grid(N / 128, M / 128, batch);
    gemm_kernel<<<grid, 256>>>(A, B, C, resid, bias, alphap,
                               M, N, K, lda, ldb, ldc,
                               sA1, sA2, sB1, sB2, sC1, sC2, bdiv,
                               tA, tB, alpha, act);
}

extern "C" void kernel_launch(void* const* d_in, const int* in_sizes, int n_in,
                              void* d_out, int out_size)
{
    const int*   x    = (const int*)d_in[0];
    const float* mem  = (const float*)d_in[1];
    const float* lmem = (const float*)d_in[2];
    const float* temb = (const float*)d_in[3];
    const float* pemb = (const float*)d_in[4];
    const float* ag   = (const float*)d_in[5];
    const float* ab   = (const float*)d_in[6];
    const float* awq  = (const float*)d_in[7];
    const float* awkv = (const float*)d_in[8];
    const float* awo  = (const float*)d_in[9];
    const float* abo  = (const float*)d_in[10];
    const float* fg   = (const float*)d_in[11];
    const float* fb   = (const float*)d_in[12];
    const float* fw1  = (const float*)d_in[13];
    const float* fb1  = (const float*)d_in[14];
    const float* fw2  = (const float*)d_in[15];
    const float* fb2  = (const float*)d_in[16];
    const float* lw   = (const float*)d_in[17];
    const float* lb   = (const float*)d_in[18];
    const float* mwq  = (const float*)d_in[19];
    const float* mwkv = (const float*)d_in[20];
    const float* mwo  = (const float*)d_in[21];
    const float* rez  = (const float*)d_in[22];

    float* out        = (float*)d_out;
    float* out_logits = out;
    float* out_mem    = out + 65536000LL;               // (4,2,1024,1024)
    float* out_lmem   = out_mem + 8388608LL;            // (4,2,256,1024)

    float* S = nullptr;
    cudaGetSymbolAddress((void**)&S, g_scratch);
    float* H    = S;
    float* HID  = H    + SZ_H;
    float* LNB  = HID  + SZ_HID;
    float* Q    = LNB  + SZ_LN;
    float* KV   = Q    + SZ_Q;
    float* QK   = KV   + SZ_KV;
    float* QPE  = QK   + SZ_QK;
    float* AOUT = QPE  + SZ_QPE;
    float* FFB  = AOUT + SZ_AOUT;
    float* NL   = FFB  + SZ_FF;
    float* MQ   = NL   + SZ_NL;
    float* MKV  = MQ   + SZ_MQ;
    float* CTX  = MKV  + SZ_MKV;
    float* MOUT = CTX  + SZ_CTX;

    // 1. token embedding
    embed_kernel<<<NB * NSEQ, 256>>>(x, temb, H);

    for (int i = 0; i < NDEPTH; i++) {
        // hiddens.append(h)
        cudaMemcpyAsync(HID + (long long)i * SZ_H, H, SZ_H * sizeof(float),
                        cudaMemcpyDeviceToDevice);

        // a_in = LN(h, g, b)
        layernorm_kernel<<<NB * NSEQ, 256>>>(H, ag + i * NDIM, ab + i * NDIM, LNB);

        // q = a_in @ wq
        gemm(LNB, awq + (long long)i * 1048576, Q, 2048, 1024, 1024, 1024, 1024, 1024);

        // kv = concat(lmem_i, mem_i, a_in) @ wkv  -> (B, 2304, 2048), batched over b
        const float* awkv_i = awkv + (long long)i * 2097152;
        gemm(lmem + (long long)i * 524288, awkv_i, KV,
             256, 2048, 1024, 1024, 2048, 2048, 2, 1,
             262144, 0, 0, 0, 4718592, 0);
        gemm(mem + (long long)i * 2097152, awkv_i, KV + 524288,
             1024, 2048, 1024, 1024, 2048, 2048, 2, 1,
             1048576, 0, 0, 0, 4718592, 0);
        gemm(LNB, awkv_i, KV + 2621440,
             1024, 2048, 1024, 1024, 2048, 2048, 2, 1,
             1048576, 0, 0, 0, 4718592, 0);

        // dots_qk[b,h] = q[b,:,h*128:] @ k[b,:,h*128:]^T   (NT, batch=16=b*8+h)
        gemm(Q, KV, QK, 1024, 2304, 128, 1024, 2048, 2304, 16, 8,
             1048576, 128, 4718592, 128, 18874368, 2359296, 0, 1);

        // dots_pe[b,h] = q[b,:,h*128:] @ pe[h]^T
        gemm(Q, pemb, QPE, 1024, 2304, 128, 1024, 128, 2304, 16, 8,
             1048576, 128, 0, 294912, 18874368, 2359296, 0, 1);

        // fused rel_shift + mask + softmax (in place into QK)
        attn_softmax_kernel<<<dim3(1024, 16), 256>>>(QK, QPE);

        // attn_out[b,:,h*128:] = attn[b,h] @ v[b,:,h*128:]
        gemm(QK, KV + 1024, AOUT, 1024, 128, 2304, 2304, 2048, 1024, 16, 8,
             18874368, 2359296, 4718592, 128, 1048576, 128);

        // h = h + attn_out @ wo + bo
        gemm(AOUT, awo + (long long)i * 1048576, H, 2048, 1024, 1024, 1024, 1024, 1024,
             1, 1, 0, 0, 0, 0, 0, 0, 0, 0, abo + i * NDIM, H);

        // f_in = LN(h)
        layernorm_kernel<<<NB * NSEQ, 256>>>(H, fg + i * NDIM, fb + i * NDIM, LNB);

        // ff = gelu(f_in @ w1 + b1)
        gemm(LNB, fw1 + (long long)i * 4194304, FFB, 2048, 4096, 1024, 1024, 4096, 4096,
             1, 1, 0, 0, 0, 0, 0, 0, 0, 0, fb1 + i * NFF, nullptr, nullptr, 1.f, 1);

        // h = h + ff @ w2 + b2
        gemm(FFB, fw2 + (long long)i * 4194304, H, 2048, 1024, 4096, 4096, 1024, 1024,
             1, 1, 0, 0, 0, 0, 0, 0, 0, 0, fb2 + i * NDIM, H);
    }

    // logits = h @ logits_w + logits_b
    gemm(H, lw, out_logits, 2048, 32000, 1024, 1024, 32000, 32000,
         1, 1, 0, 0, 0, 0, 0, 0, 0, 0, lb, nullptr);

    // ----------------- memory network -----------------
    // nl = LN(lmem)  (no affine), rows = 4*2*256 = 2048
    layernorm_kernel<<<2048, 256>>>(lmem, nullptr, nullptr, NL);

    // q = nl @ wq
    gemm(NL, mwq, MQ, 2048, 1024, 1024, 1024, 1024, 1024);

    // kv = concat(nl, mem, hiddens) @ wkv  -> (8, 2304, 2048), batched over mb
    gemm(NL, mwkv, MKV, 256, 2048, 1024, 1024, 2048, 2048, 8, 1,
         262144, 0, 0, 0, 4718592, 0);
    gemm(mem, mwkv, MKV + 524288, 1024, 2048, 1024, 1024, 2048, 2048, 8, 1,
         1048576, 0, 0, 0, 4718592, 0);
    gemm(HID, mwkv, MKV + 2621440, 1024, 2048, 1024, 1024, 2048, 2048, 8, 1,
         1048576, 0, 0, 0, 4718592, 0);

    // q softmax over DH; k softmax over n
    head_softmax_kernel<<<2048, 256>>>(MQ);
    col_softmax_kernel<<<dim3(8, 8), 128>>>(MKV);

    // ctx[mb,h] = k[mb,:,h*128:]^T @ v[mb,:,1024+h*128:]   (TN, batch 64)
    gemm(MKV, MKV + 1024, CTX, 128, 128, 2304, 2048, 2048, 128, 64, 8,
         4718592, 128, 4718592, 128, 131072, 16384, 1, 0);

    // out[mb,:,h*128:] = q[mb,:,h*128:] @ ctx[mb,h]
    gemm(MQ, CTX, MOUT, 256, 128, 128, 1024, 128, 1024, 64, 8,
         262144, 128, 131072, 16384, 262144, 128);

    // next_lmem = out @ wo * rezero + lmem
    gemm(MOUT, mwo, out_lmem, 2048, 1024, 1024, 1024, 1024, 1024,
         1, 1, 0, 0, 0, 0, 0, 0, 0, 0, nullptr, lmem, rez, 1.f, 0);

    // next_mem = hiddens (concat(mem, hiddens)[:, :, -1024:] == hiddens)
    cudaMemcpyAsync(out_mem, HID, SZ_HID * sizeof(float), cudaMemcpyDeviceToDevice);
}

// round 3
// speedup vs baseline: 1.6288x; 1.6288x over previous
#include <cuda_runtime.h>
#include <cuda_bf16.h>
#include <math.h>
#include <stdint.h>

// ---------------------------------------------------------------------------
// MemoryTransformerXL forward. GEMMs on tensor cores via split-bf16 3-pass
// (fp32-equivalent precision, ~1e-5 rel err). B=2, DEPTH=4, HEADS=8, DIM=1024,
// DH=128, SEQ=1024, MEM=1024, LMEM=256, VOCAB=32000, KVL=2304, FF=4096.
// ---------------------------------------------------------------------------

#define NB (2)
#define NSEQ (1024)
#define NDIM (1024)
#define NHEADS (8)
#define NDH (128)
#define NMEM (1024)
#define NLMEM (256)
#define NKVL (2304)
#define NDEPTH (4)
#define NVOCAB (32000)
#define NFF (4096)

// scratch layout (floats)
#define SZ_H    (2097152LL)
#define SZ_HID  (8388608LL)
#define SZ_LN   (2097152LL)
#define SZ_Q    (2097152LL)
#define SZ_KV   (9437184LL)
#define SZ_QK   (37748736LL)
#define SZ_QPE  (37748736LL)
#define SZ_AOUT (2097152LL)
#define SZ_FF   (8388608LL)
#define SZ_NL   (2097152LL)
#define SZ_MQ   (2097152LL)
#define SZ_MKV  (37748736LL)
#define SZ_CTX  (1048576LL)
#define SZ_MOUT (2097152LL)
#define SZ_TOTAL (155189248LL)

__device__ float g_scratch[SZ_TOTAL];

// ---------------------------------------------------------------------------
// Tensor-core GEMM: C = act(alpha*A@B + bias) + resid, fp32 in/out.
// Split-bf16 3-pass: x = hi + lo; C += Ah*Bh + Ah*Bl + Al*Bh (fp32 accum).
// Block tile 128x128x32, 256 thr (8 warps, 2x4), warp tile 64x32, mma 16x8x16.
// transA: A stored (K,M). transB: B stored (N,K). All dims tile-divisible.
// ---------------------------------------------------------------------------

__device__ __forceinline__ void split2(float x, float y, uint32_t& h, uint32_t& l)
{
    __nv_bfloat16 hx = __float2bfloat16(x);
    __nv_bfloat16 hy = __float2bfloat16(y);
    __nv_bfloat16 lx = __float2bfloat16(x - __bfloat162float(hx));
    __nv_bfloat16 ly = __float2bfloat16(y - __bfloat162float(hy));
    h = (uint32_t)__bfloat16_as_ushort(hx) | ((uint32_t)__bfloat16_as_ushort(hy) << 16);
    l = (uint32_t)__bfloat16_as_ushort(lx) | ((uint32_t)__bfloat16_as_ushort(ly) << 16);
}

__device__ __forceinline__ void mma16816(float* c, const uint32_t* a, const uint32_t* b)
{
    asm volatile(
        "mma.sync.aligned.m16n8k16.row.col.f32.bf16.bf16.f32 "
        "{%0,%1,%2,%3},{%4,%5,%6,%7},{%8,%9},{%0,%1,%2,%3};"
        : "+f"(c[0]), "+f"(c[1]), "+f"(c[2]), "+f"(c[3])
        : "r"(a[0]), "r"(a[1]), "r"(a[2]), "r"(a[3]), "r"(b[0]), "r"(b[1]));
}

__global__ void __launch_bounds__(256, 1) gemm_kernel(
    const float* __restrict__ A, const float* __restrict__ B,
    float* __restrict__ C, const float* __restrict__ Rsrc,
    const float* __restrict__ bias, const float* __restrict__ alphap,
    int M, int N, int K, int lda, int ldb, int ldc,
    long long sA1, long long sA2, long long sB1, long long sB2,
    long long sC1, long long sC2, int bdiv,
    int transA, int transB, float alpha, int act)
{
    // smem: hi/lo bf16 planes, rows of 32 k-values stored as 16 words + 1 pad
    __shared__ uint32_t sAhi[128 * 17], sAlo[128 * 17];
    __shared__ uint32_t sBhi[128 * 17], sBlo[128 * 17];

    int bz = blockIdx.z;
    int b1 = bz / bdiv, b2 = bz - b1 * bdiv;
    A += (long long)b1 * sA1 + (long long)b2 * sA2;
    B += (long long)b1 * sB1 + (long long)b2 * sB2;
    long long offC = (long long)b1 * sC1 + (long long)b2 * sC2;
    C += offC;
    if (Rsrc) Rsrc += offC;

    int m0 = blockIdx.y * 128, n0 = blockIdx.x * 128;
    int tid = threadIdx.x;
    int warp = tid >> 5, lane = tid & 31;
    int wm = warp >> 2, wn = warp & 3;      // warp grid 2 (M) x 4 (N)
    int g = lane >> 2, t = lane & 3;

    float c[4][4][4];
#pragma unroll
    for (int mt = 0; mt < 4; mt++)
#pragma unroll
        for (int nt = 0; nt < 4; nt++)
#pragma unroll
            for (int j = 0; j < 4; j++) c[mt][nt][j] = 0.f;

    float4 ra[4], rb[4];
    int nkt = K >> 5;

    auto ldA = [&](int kt) {
        long long k0 = (long long)kt << 5;
        if (!transA) {
#pragma unroll
            for (int it = 0; it < 4; it++) {
                int v = tid + it * 256;
                int r = v >> 3, kq = (v & 7) << 2;
                ra[it] = *(const float4*)(A + (long long)(m0 + r) * lda + k0 + kq);
            }
        } else {
#pragma unroll
            for (int it = 0; it < 4; it++) {
                int v = tid + it * 256;
                int k = v >> 5, mq = (v & 31) << 2;
                ra[it] = *(const float4*)(A + (k0 + k) * lda + m0 + mq);
            }
        }
    };
    auto ldB = [&](int kt) {
        long long k0 = (long long)kt << 5;
        if (!transB) {
#pragma unroll
            for (int it = 0; it < 4; it++) {
                int v = tid + it * 256;
                int k = v >> 5, nq = (v & 31) << 2;
                rb[it] = *(const float4*)(B + (k0 + k) * ldb + n0 + nq);
            }
        } else {
#pragma unroll
            for (int it = 0; it < 4; it++) {
                int v = tid + it * 256;
                int n = v >> 3, kq = (v & 7) << 2;
                rb[it] = *(const float4*)(B + (long long)(n0 + n) * ldb + k0 + kq);
            }
        }
    };
    auto stA = [&]() {
        if (!transA) {
#pragma unroll
            for (int it = 0; it < 4; it++) {
                int v = tid + it * 256;
                int r = v >> 3, kq = (v & 7) << 2;
                uint32_t h0, l0, h1, l1;
                split2(ra[it].x, ra[it].y, h0, l0);
                split2(ra[it].z, ra[it].w, h1, l1);
                int w = r * 17 + (kq >> 1);
                sAhi[w] = h0; sAhi[w + 1] = h1;
                sAlo[w] = l0; sAlo[w + 1] = l1;
            }
        } else {
#pragma unroll
            for (int it = 0; it < 4; it++) {
                int v = tid + it * 256;
                int k = v >> 5, mq = (v & 31) << 2;
                float f[4] = {ra[it].x, ra[it].y, ra[it].z, ra[it].w};
#pragma unroll
                for (int j = 0; j < 4; j++) {
                    __nv_bfloat16 h = __float2bfloat16(f[j]);
                    __nv_bfloat16 l = __float2bfloat16(f[j] - __bfloat162float(h));
                    ((__nv_bfloat16*)sAhi)[(mq + j) * 34 + k] = h;
                    ((__nv_bfloat16*)sAlo)[(mq + j) * 34 + k] = l;
                }
            }
        }
    };
    auto stB = [&]() {
        if (!transB) {
#pragma unroll
            for (int it = 0; it < 4; it++) {
                int v = tid + it * 256;
                int k = v >> 5, nq = (v & 31) << 2;
                float f[4] = {rb[it].x, rb[it].y, rb[it].z, rb[it].w};
#pragma unroll
                for (int j = 0; j < 4; j++) {
                    __nv_bfloat16 h = __float2bfloat16(f[j]);
                    __nv_bfloat16 l = __float2bfloat16(f[j] - __bfloat162float(h));
                    ((__nv_bfloat16*)sBhi)[(nq + j) * 34 + k] = h;
                    ((__nv_bfloat16*)sBlo)[(nq + j) * 34 + k] = l;
                }
            }
        } else {
#pragma unroll
            for (int it = 0; it < 4; it++) {
                int v = tid + it * 256;
                int n = v >> 3, kq = (v & 7) << 2;
                uint32_t h0, l0, h1, l1;
                split2(rb[it].x, rb[it].y, h0, l0);
                split2(rb[it].z, rb[it].w, h1, l1);
                int w = n * 17 + (kq >> 1);
                sBhi[w] = h0; sBhi[w + 1] = h1;
                sBlo[w] = l0; sBlo[w + 1] = l1;
            }
        }
    };

    ldA(0); ldB(0);

    for (int kt = 0; kt < nkt; kt++) {
        stA(); stB();
        __syncthreads();
        if (kt + 1 < nkt) { ldA(kt + 1); ldB(kt + 1); }

#pragma unroll
        for (int ks = 0; ks < 2; ks++) {
            int kw = ks * 8 + t;
            uint32_t bh[4][2], bl[4][2];
#pragma unroll
            for (int nt = 0; nt < 4; nt++) {
                int col = wn * 32 + nt * 8 + g;
                bh[nt][0] = sBhi[col * 17 + kw];
                bh[nt][1] = sBhi[col * 17 + kw + 4];
                bl[nt][0] = sBlo[col * 17 + kw];
                bl[nt][1] = sBlo[col * 17 + kw + 4];
            }
#pragma unroll
            for (int mt = 0; mt < 4; mt++) {
                int r0 = wm * 64 + mt * 16;
                uint32_t ah[4], al[4];
                ah[0] = sAhi[(r0 + g) * 17 + kw];
                ah[1] = sAhi[(r0 + g + 8) * 17 + kw];
                ah[2] = sAhi[(r0 + g) * 17 + kw + 4];
                ah[3] = sAhi[(r0 + g + 8) * 17 + kw + 4];
                al[0] = sAlo[(r0 + g) * 17 + kw];
                al[1] = sAlo[(r0 + g + 8) * 17 + kw];
                al[2] = sAlo[(r0 + g) * 17 + kw + 4];
                al[3] = sAlo[(r0 + g + 8) * 17 + kw + 4];
#pragma unroll
                for (int nt = 0; nt < 4; nt++) {
                    mma16816(c[mt][nt], ah, bh[nt]);
                    mma16816(c[mt][nt], ah, bl[nt]);
                    mma16816(c[mt][nt], al, bh[nt]);
                }
            }
        }
        __syncthreads();
    }

    float aval = alphap ? *alphap : alpha;
#pragma unroll
    for (int mt = 0; mt < 4; mt++) {
#pragma unroll
        for (int nt = 0; nt < 4; nt++) {
            int row = m0 + wm * 64 + mt * 16 + g;
            int col = n0 + wn * 32 + nt * 8 + 2 * t;
            float* cc = c[mt][nt];
#pragma unroll
            for (int h = 0; h < 2; h++) {
                int r = row + h * 8;
                float e0 = cc[h * 2 + 0] * aval;
                float e1 = cc[h * 2 + 1] * aval;
                if (bias) { e0 += bias[col]; e1 += bias[col + 1]; }
                if (act == 1) {
                    e0 = 0.5f * e0 * (1.f + erff(e0 * 0.70710678118654752f));
                    e1 = 0.5f * e1 * (1.f + erff(e1 * 0.70710678118654752f));
                }
                if (Rsrc) {
                    e0 += Rsrc[(long long)r * ldc + col];
                    e1 += Rsrc[(long long)r * ldc + col + 1];
                }
                float2 o = make_float2(e0, e1);
                *(float2*)(C + (long long)r * ldc + col) = o;
            }
        }
    }
}

// ---------------------------------------------------------------------------
// Embedding gather
// ---------------------------------------------------------------------------
__global__ void embed_kernel(const int* __restrict__ x, const float* __restrict__ emb,
                             float* __restrict__ h)
{
    int row = blockIdx.x;
    int tok = x[row];
    *(float4*)(h + (long long)row * NDIM + threadIdx.x * 4) =
        *(const float4*)(emb + (long long)tok * NDIM + threadIdx.x * 4);
}

// ---------------------------------------------------------------------------
// LayerNorm over last dim (1024)
// ---------------------------------------------------------------------------
__global__ void layernorm_kernel(const float* __restrict__ x, const float* __restrict__ g,
                                 const float* __restrict__ b, float* __restrict__ y)
{
    int tid = threadIdx.x;
    long long base = (long long)blockIdx.x * NDIM;
    float4 v = *(const float4*)(x + base + tid * 4);
    float s = v.x + v.y + v.z + v.w;
    float q = v.x * v.x + v.y * v.y + v.z * v.z + v.w * v.w;
#pragma unroll
    for (int o = 16; o > 0; o >>= 1) {
        s += __shfl_xor_sync(0xffffffffu, s, o);
        q += __shfl_xor_sync(0xffffffffu, q, o);
    }
    __shared__ float rs[8], rq[8];
    if ((tid & 31) == 0) { rs[tid >> 5] = s; rq[tid >> 5] = q; }
    __syncthreads();
    s = 0.f; q = 0.f;
#pragma unroll
    for (int j = 0; j < 8; j++) { s += rs[j]; q += rq[j]; }
    float mu = s * (1.f / 1024.f);
    float var = q * (1.f / 1024.f) - mu * mu;
    float rstd = rsqrtf(var + 1e-5f);
    float4 o;
    if (g) {
        float4 gv = *(const float4*)(g + tid * 4);
        float4 bv = *(const float4*)(b + tid * 4);
        o.x = (v.x - mu) * rstd * gv.x + bv.x;
        o.y = (v.y - mu) * rstd * gv.y + bv.y;
        o.z = (v.z - mu) * rstd * gv.z + bv.z;
        o.w = (v.w - mu) * rstd * gv.w + bv.w;
    } else {
        o.x = (v.x - mu) * rstd; o.y = (v.y - mu) * rstd;
        o.z = (v.z - mu) * rstd; o.w = (v.w - mu) * rstd;
    }
    *(float4*)(y + base + tid * 4) = o;
}

// ---------------------------------------------------------------------------
// Attention softmax with fused rel_shift + causal mask (in place into qk)
// ---------------------------------------------------------------------------
__global__ void attn_softmax_kernel(float* __restrict__ qk, const float* __restrict__ qpe)
{
    const float scale = 0.08838834764831845f;
    int r = blockIdx.x;
    long long base = ((long long)blockIdx.y * NSEQ + r) * NKVL;
    float* row = qk + base;
    const float* prow = qpe + base;
    int tid = threadIdx.x;
    int nvalid = r + 1281;

    float vals[9];
    float lmax = -3.4e38f;
#pragma unroll
    for (int it = 0; it < 9; it++) {
        int c = tid + it * 256;
        float v = -3.4e38f;
        if (c < nvalid) v = scale * (row[c] + prow[c + 1023 - r]);
        vals[it] = v;
        lmax = fmaxf(lmax, v);
    }
    __shared__ float red[8];
#pragma unroll
    for (int o = 16; o > 0; o >>= 1) lmax = fmaxf(lmax, __shfl_xor_sync(0xffffffffu, lmax, o));
    if ((tid & 31) == 0) red[tid >> 5] = lmax;
    __syncthreads();
    float m = red[0];
#pragma unroll
    for (int j = 1; j < 8; j++) m = fmaxf(m, red[j]);
    __syncthreads();

    float lsum = 0.f;
#pragma unroll
    for (int it = 0; it < 9; it++) {
        float e = expf(vals[it] - m);
        vals[it] = e;
        lsum += e;
    }
#pragma unroll
    for (int o = 16; o > 0; o >>= 1) lsum += __shfl_xor_sync(0xffffffffu, lsum, o);
    if ((tid & 31) == 0) red[tid >> 5] = lsum;
    __syncthreads();
    float ssum = 0.f;
#pragma unroll
    for (int j = 0; j < 8; j++) ssum += red[j];
    float inv = 1.f / ssum;
#pragma unroll
    for (int it = 0; it < 9; it++) row[tid + it * 256] = vals[it] * inv;
}

// ---------------------------------------------------------------------------
// Memory-net q softmax (per 128-wide head chunk)
// ---------------------------------------------------------------------------
__global__ void head_softmax_kernel(float* __restrict__ q)
{
    const float scale = 0.29730177875068026f;
    int w = threadIdx.x >> 5, lane = threadIdx.x & 31;
    float* p = q + (long long)blockIdx.x * NDIM + w * NDH + lane * 4;
    float4 v = *(float4*)p;
    v.x *= scale; v.y *= scale; v.z *= scale; v.w *= scale;
    float m = fmaxf(fmaxf(v.x, v.y), fmaxf(v.z, v.w));
#pragma unroll
    for (int o = 16; o > 0; o >>= 1) m = fmaxf(m, __shfl_xor_sync(0xffffffffu, m, o));
    float4 e;
    e.x = expf(v.x - m); e.y = expf(v.y - m); e.z = expf(v.z - m); e.w = expf(v.w - m);
    float s = e.x + e.y + e.z + e.w;
#pragma unroll
    for (int o = 16; o > 0; o >>= 1) s += __shfl_xor_sync(0xffffffffu, s, o);
    float inv = 1.f / s;
    e.x *= inv; e.y *= inv; e.z *= inv; e.w *= inv;
    *(float4*)p = e;
}

// ---------------------------------------------------------------------------
// Memory-net k softmax over n (axis=-2)
// ---------------------------------------------------------------------------
__global__ void col_softmax_kernel(float* __restrict__ kbuf)
{
    const float scale = 0.29730177875068026f;
    int mb = blockIdx.y;
    int col = blockIdx.x * 128 + threadIdx.x;
    float* p = kbuf + (long long)mb * NKVL * 2048 + col;
    float m = -3.4e38f, s = 0.f;
    for (int n = 0; n < NKVL; n++) {
        float v = p[(long long)n * 2048] * scale;
        if (v > m) { s = s * expf(m - v) + 1.f; m = v; }
        else s += expf(v - m);
    }
    float inv = 1.f / s;
    for (int n = 0; n < NKVL; n++) {
        float v = p[(long long)n * 2048] * scale;
        p[(long long)n * 2048] = expf(v - m) * inv;
    }
}

// ---------------------------------------------------------------------------
// Host-side launcher
// ---------------------------------------------------------------------------
static void gemm(const float* A, const float* B, float* C,
                 int M, int N, int K, int lda, int ldb, int ldc,
                 int batch = 1, int bdiv = 1,
                 long long sA1 = 0, long long sA2 = 0,
                 long long sB1 = 0, long long sB2 = 0,
                 long long sC1 = 0, long long sC2 = 0,
                 int tA = 0, int tB = 0,
                 const float* bias = nullptr, const float* resid = nullptr,
                 const float* alphap = nullptr, float alpha = 1.f, int act = 0)
{
    dim3 grid(N / 128, M / 128, batch);
    gemm_kernel<<<grid, 256>>>(A, B, C, resid, bias, alphap,
                               M, N, K, lda, ldb, ldc,
                               sA1, sA2, sB1, sB2, sC1, sC2, bdiv,
                               tA, tB, alpha, act);
}

extern "C" void kernel_launch(void* const* d_in, const int* in_sizes, int n_in,
                              void* d_out, int out_size)
{
    const int*   x    = (const int*)d_in[0];
    const float* mem  = (const float*)d_in[1];
    const float* lmem = (const float*)d_in[2];
    const float* temb = (const float*)d_in[3];
    const float* pemb = (const float*)d_in[4];
    const float* ag   = (const float*)d_in[5];
    const float* ab   = (const float*)d_in[6];
    const float* awq  = (const float*)d_in[7];
    const float* awkv = (const float*)d_in[8];
    const float* awo  = (const float*)d_in[9];
    const float* abo  = (const float*)d_in[10];
    const float* fg   = (const float*)d_in[11];
    const float* fb   = (const float*)d_in[12];
    const float* fw1  = (const float*)d_in[13];
    const float* fb1  = (const float*)d_in[14];
    const float* fw2  = (const float*)d_in[15];
    const float* fb2  = (const float*)d_in[16];
    const float* lw   = (const float*)d_in[17];
    const float* lb   = (const float*)d_in[18];
    const float* mwq  = (const float*)d_in[19];
    const float* mwkv = (const float*)d_in[20];
    const float* mwo  = (const float*)d_in[21];
    const float* rez  = (const float*)d_in[22];

    float* out        = (float*)d_out;
    float* out_logits = out;
    float* out_mem    = out + 65536000LL;
    float* out_lmem   = out_mem + 8388608LL;

    float* S = nullptr;
    cudaGetSymbolAddress((void**)&S, g_scratch);
    float* H    = S;
    float* HID  = H    + SZ_H;
    float* LNB  = HID  + SZ_HID;
    float* Q    = LNB  + SZ_LN;
    float* KV   = Q    + SZ_Q;
    float* QK   = KV   + SZ_KV;
    float* QPE  = QK   + SZ_QK;
    float* AOUT = QPE  + SZ_QPE;
    float* FFB  = AOUT + SZ_AOUT;
    float* NL   = FFB  + SZ_FF;
    float* MQ   = NL   + SZ_NL;
    float* MKV  = MQ   + SZ_MQ;
    float* CTX  = MKV  + SZ_MKV;
    float* MOUT = CTX  + SZ_CTX;

    embed_kernel<<<NB * NSEQ, 256>>>(x, temb, H);

    for (int i = 0; i < NDEPTH; i++) {
        cudaMemcpyAsync(HID + (long long)i * SZ_H, H, SZ_H * sizeof(float),
                        cudaMemcpyDeviceToDevice);

        layernorm_kernel<<<NB * NSEQ, 256>>>(H, ag + i * NDIM, ab + i * NDIM, LNB);

        gemm(LNB, awq + (long long)i * 1048576, Q, 2048, 1024, 1024, 1024, 1024, 1024);

        const float* awkv_i = awkv + (long long)i * 2097152;
        gemm(lmem + (long long)i * 524288, awkv_i, KV,
             256, 2048, 1024, 1024, 2048, 2048, 2, 1,
             262144, 0, 0, 0, 4718592, 0);
        gemm(mem + (long long)i * 2097152, awkv_i, KV + 524288,
             1024, 2048, 1024, 1024, 2048, 2048, 2, 1,
             1048576, 0, 0, 0, 4718592, 0);
        gemm(LNB, awkv_i, KV + 2621440,
             1024, 2048, 1024, 1024, 2048, 2048, 2, 1,
             1048576, 0, 0, 0, 4718592, 0);

        gemm(Q, KV, QK, 1024, 2304, 128, 1024, 2048, 2304, 16, 8,
             1048576, 128, 4718592, 128, 18874368, 2359296, 0, 1);

        gemm(Q, pemb, QPE, 1024, 2304, 128, 1024, 128, 2304, 16, 8,
             1048576, 128, 0, 294912, 18874368, 2359296, 0, 1);

        attn_softmax_kernel<<<dim3(1024, 16), 256>>>(QK, QPE);

        gemm(QK, KV + 1024, AOUT, 1024, 128, 2304, 2304, 2048, 1024, 16, 8,
             18874368, 2359296, 4718592, 128, 1048576, 128);

        gemm(AOUT, awo + (long long)i * 1048576, H, 2048, 1024, 1024, 1024, 1024, 1024,
             1, 1, 0, 0, 0, 0, 0, 0, 0, 0, abo + i * NDIM, H);

        layernorm_kernel<<<NB * NSEQ, 256>>>(H, fg + i * NDIM, fb + i * NDIM, LNB);

        gemm(LNB, fw1 + (long long)i * 4194304, FFB, 2048, 4096, 1024, 1024, 4096, 4096,
             1, 1, 0, 0, 0, 0, 0, 0, 0, 0, fb1 + i * NFF, nullptr, nullptr, 1.f, 1);

        gemm(FFB, fw2 + (long long)i * 4194304, H, 2048, 1024, 4096, 4096, 1024, 1024,
             1, 1, 0, 0, 0, 0, 0, 0, 0, 0, fb2 + i * NDIM, H);
    }

    gemm(H, lw, out_logits, 2048, 32000, 1024, 1024, 32000, 32000,
         1, 1, 0, 0, 0, 0, 0, 0, 0, 0, lb, nullptr);

    // ----------------- memory network -----------------
    layernorm_kernel<<<2048, 256>>>(lmem, nullptr, nullptr, NL);

    gemm(NL, mwq, MQ, 2048, 1024, 1024, 1024, 1024, 1024);

    gemm(NL, mwkv, MKV, 256, 2048, 1024, 1024, 2048, 2048, 8, 1,
         262144, 0, 0, 0, 4718592, 0);
    gemm(mem, mwkv, MKV + 524288, 1024, 2048, 1024, 1024, 2048, 2048, 8, 1,
         1048576, 0, 0, 0, 4718592, 0);
    gemm(HID, mwkv, MKV + 2621440, 1024, 2048, 1024, 1024, 2048, 2048, 8, 1,
         1048576, 0, 0, 0, 4718592, 0);

    head_softmax_kernel<<<2048, 256>>>(MQ);
    col_softmax_kernel<<<dim3(8, 8), 128>>>(MKV);

    gemm(MKV, MKV + 1024, CTX, 128, 128, 2304, 2048, 2048, 128, 64, 8,
         4718592, 128, 4718592, 128, 131072, 16384, 1, 0);

    gemm(MQ, CTX, MOUT, 256, 128, 128, 1024, 128, 1024, 64, 8,
         262144, 128, 131072, 16384, 262144, 128);

    gemm(MOUT, mwo, out_lmem, 2048, 1024, 1024, 1024, 1024, 1024,
         1, 1, 0, 0, 0, 0, 0, 0, 0, 0, nullptr, lmem, rez, 1.f, 0);

    cudaMemcpyAsync(out_mem, HID, SZ_HID * sizeof(float), cudaMemcpyDeviceToDevice);
}